// round 9
// baseline (speedup 1.0000x reference)
#include <cuda_runtime.h>
#include <math.h>

#define BB 256
#define NCH 32
#define TT 2000
#define NTF 4
#define NSF 40
#define NSUB 20
#define TK 25
#define NPAIR 210
#define NCHUNK 8
#define TC 250
#define ZW 288           // z row width (taus 0..279 used)
#define YSS 258
#define NSWEEP 6
#define EIG_WPB 8        // matrices (warps) per eig block

typedef unsigned long long ull;

// Static scratch (no runtime allocation allowed)
__device__ float g_W2T[32 * 80];                       // [c*80 + sg]
__device__ float g_z[(size_t)BB * NCHUNK * 80 * ZW];   // 188.7 MB
__device__ float g_part[NCHUNK][BB][420];

__device__ __forceinline__ void fma2(ull& d, ull a, ull b) {
    asm("fma.rn.f32x2 %0, %1, %2, %0;" : "+l"(d) : "l"(a), "l"(b));
}
__device__ __forceinline__ ull pack2(float lo, float hi) {
    ull r; asm("mov.b64 %0, {%1, %2};" : "=l"(r) : "f"(lo), "f"(hi)); return r;
}
__device__ __forceinline__ float2 unpack2(ull v) {
    float2 f; asm("mov.b64 {%0, %1}, %2;" : "=f"(f.x), "=f"(f.y) : "l"(v)); return f;
}

// ---------------------------------------------------------------------------
// W2T[c][sg] = sum_f W_bimap[s,f] * conv2_w[f,g,c],  sg = s*4+g
// ---------------------------------------------------------------------------
__global__ void prep_kernel(const float* __restrict__ conv2_w,
                            const float* __restrict__ W_bimap) {
    int idx = blockIdx.x * blockDim.x + threadIdx.x;
    if (idx < 2560) {
        int c = idx / 80, sg = idx % 80;
        int s = sg / 4, g = sg % 4;
        float acc = 0.f;
        #pragma unroll 8
        for (int f = 0; f < NSF; ++f)
            acc += W_bimap[s * NSF + f] * conv2_w[f * 128 + g * 32 + c];
        g_W2T[c * 80 + sg] = acc;
    }
}

// ---------------------------------------------------------------------------
// Kernel A: z[sg, tau] = sum_c W2[sg,c] * x[c, t0-12+tau]  (GEMM)
// ---------------------------------------------------------------------------
__global__ void __launch_bounds__(128)
gemm_kernel(const float* __restrict__ x) {
    __shared__ float xs[32][ZW];       // 36.9 KB
    __shared__ float w2d[32][160];     // duplicated weights, 20.5 KB

    const int tid = threadIdx.x;
    const int chunk = blockIdx.x, b = blockIdx.y;
    const int t0 = chunk * TC;
    const float* __restrict__ xb = x + (size_t)b * NCH * TT;

    for (int idx = tid; idx < 32 * ZW; idx += 128) {
        int c = idx / ZW, tt = idx % ZW;
        int gi = t0 - 12 + tt;
        if (gi < 0) gi = -gi;
        if (gi >= TT) gi = 2 * TT - 2 - gi;
        xs[c][tt] = xb[c * TT + gi];
    }
    for (int idx = tid; idx < 2560; idx += 128) {
        int c = idx / 80, sg = idx % 80;
        float w = g_W2T[idx];
        w2d[c][2 * sg] = w;
        w2d[c][2 * sg + 1] = w;
    }
    __syncthreads();

    const int warp = tid >> 5, lane = tid & 31;
    if (lane < 28) {
        const int tau0 = lane * 10;
        float* zbase = &g_z[((size_t)(b * NCHUNK + chunk) * 80) * ZW];

        #pragma unroll 1
        for (int pass = 0; pass < 5; ++pass) {
            const int sg0 = (pass * 4 + warp) * 4;
            ull acc[4][5];
            #pragma unroll
            for (int q = 0; q < 4; ++q)
                #pragma unroll
                for (int p = 0; p < 5; ++p) acc[q][p] = 0;

            #pragma unroll 2
            for (int c = 0; c < NCH; ++c) {
                const ull* xp = (const ull*)&xs[c][tau0];
                ull xv0 = xp[0], xv1 = xp[1], xv2 = xp[2], xv3 = xp[3], xv4 = xp[4];
                const ull* wdp = (const ull*)&w2d[c][2 * sg0];   // broadcast
                ull wd0 = wdp[0], wd1 = wdp[1], wd2 = wdp[2], wd3 = wdp[3];
                fma2(acc[0][0], xv0, wd0); fma2(acc[0][1], xv1, wd0);
                fma2(acc[0][2], xv2, wd0); fma2(acc[0][3], xv3, wd0);
                fma2(acc[0][4], xv4, wd0);
                fma2(acc[1][0], xv0, wd1); fma2(acc[1][1], xv1, wd1);
                fma2(acc[1][2], xv2, wd1); fma2(acc[1][3], xv3, wd1);
                fma2(acc[1][4], xv4, wd1);
                fma2(acc[2][0], xv0, wd2); fma2(acc[2][1], xv1, wd2);
                fma2(acc[2][2], xv2, wd2); fma2(acc[2][3], xv3, wd2);
                fma2(acc[2][4], xv4, wd2);
                fma2(acc[3][0], xv0, wd3); fma2(acc[3][1], xv1, wd3);
                fma2(acc[3][2], xv2, wd3); fma2(acc[3][3], xv3, wd3);
                fma2(acc[3][4], xv4, wd3);
            }
            #pragma unroll
            for (int q = 0; q < 4; ++q) {
                ull* zr = (ull*)(zbase + (size_t)(sg0 + q) * ZW + tau0);
                #pragma unroll
                for (int p = 0; p < 5; ++p) zr[p] = acc[q][p];
            }
        }
    }
}

// ---------------------------------------------------------------------------
// Kernel B: y[s,t] = sum_g sum_k w1[g,k] z[s*4+g, t+k]; then covariance.
// z slabs register-double-buffered (prefetch n+1 while computing n).
// ---------------------------------------------------------------------------
__global__ void __launch_bounds__(128)
conv_cov_kernel(const float* __restrict__ w1) {
    __shared__ float zs[16 * ZW];    // 18.4 KB (aliased by red after slabs)
    __shared__ float ys[20 * YSS];   // 20.6 KB
    __shared__ float w1p[224];
    float* red = zs;

    const int tid = threadIdx.x;
    const int chunk = blockIdx.x, b = blockIdx.y;
    const float* zbase = &g_z[((size_t)(b * NCHUNK + chunk) * 80) * ZW];

    if (tid < 104) {
        int phase = tid / 52, rem = tid % 52, g = rem / 13, i = rem % 13;
        float lo, hi;
        if (phase == 0) {
            lo = w1[g * TK + 2 * i];
            hi = (i < 12) ? w1[g * TK + 2 * i + 1] : 0.f;
        } else {
            lo = (i == 0) ? 0.f : w1[g * TK + 2 * i - 1];
            hi = w1[g * TK + 2 * i];
        }
        int base = (phase * 4 + g) * 28 + 2 * i;
        w1p[base] = lo; w1p[base + 1] = hi;
    }
    if (tid >= 104 && tid < 120) {
        int s = tid - 104;
        w1p[(s >> 1) * 28 + 26 + (s & 1)] = 0.f;
    }

    // preload slab 0 into registers (9 float4 per thread covers 4608 floats)
    float4 pf[9];
    {
        const float4* src = (const float4*)zbase;
        #pragma unroll
        for (int r = 0; r < 9; ++r) {
            int i = tid + r * 128;
            if (i < 16 * ZW / 4) pf[r] = src[i];
        }
    }
    __syncthreads();

    const ull* wp = (const ull*)w1p;

    for (int slb = 0; slb < 5; ++slb) {
        // commit prefetched slab to smem
        {
            float4* dst = (float4*)zs;
            #pragma unroll
            for (int r = 0; r < 9; ++r) {
                int i = tid + r * 128;
                if (i < 16 * ZW / 4) dst[i] = pf[r];
            }
        }
        __syncthreads();

        // prefetch next slab while computing this one
        if (slb < 4) {
            const float4* src = (const float4*)(zbase + (size_t)(slb + 1) * 16 * ZW);
            #pragma unroll
            for (int r = 0; r < 9; ++r) {
                int i = tid + r * 128;
                if (i < 16 * ZW / 4) pf[r] = src[i];
            }
        }

        {
            const int s_loc = tid >> 5, ti = tid & 31;
            const int tl = ti * 8;
            ull accP[8];
            #pragma unroll
            for (int o = 0; o < 8; ++o) accP[o] = 0;

            #pragma unroll
            for (int g = 0; g < 4; ++g) {
                const ull* zrow = (const ull*)&zs[(s_loc * 4 + g) * ZW + tl];
                ull win[16];
                #pragma unroll
                for (int j = 0; j < 16; ++j) win[j] = zrow[j];
                #pragma unroll
                for (int i = 0; i < 13; ++i) {
                    ull wa = wp[g * 14 + i], wb = wp[(4 + g) * 14 + i];
                    #pragma unroll
                    for (int m = 0; m < 4; ++m) {
                        fma2(accP[2 * m],     win[m + i], wa);
                        fma2(accP[2 * m + 1], win[m + i], wb);
                    }
                }
            }
            const int s = slb * 4 + s_loc;
            #pragma unroll
            for (int m = 0; m < 4; ++m) {
                float2 e = unpack2(accP[2 * m]);
                float2 o = unpack2(accP[2 * m + 1]);
                *(float2*)&ys[s * YSS + tl + 2 * m] = make_float2(e.x + e.y, o.x + o.y);
            }
        }
        __syncthreads();
    }

    if (tid < 120) {
        int s = tid / 6, col = 250 + tid % 6;
        ys[s * YSS + col] = 0.f;
    }
    __syncthreads();

    // covariance: 25 4x4-tiles x 4 t-slices + 20 means
    if (tid < 100) {
        const int tile = tid >> 2, slice = tid & 3;
        const int i0 = (tile / 5) * 4, j0 = (tile % 5) * 4;
        ull acc[16];
        #pragma unroll
        for (int e = 0; e < 16; ++e) acc[e] = 0;
        for (int t4 = slice; t4 < 64; t4 += 4) {
            ull ri[4][2], rj[4][2];
            #pragma unroll
            for (int a = 0; a < 4; ++a) {
                const ull* pi = (const ull*)&ys[(i0 + a) * YSS + 4 * t4];
                const ull* pj = (const ull*)&ys[(j0 + a) * YSS + 4 * t4];
                ri[a][0] = pi[0]; ri[a][1] = pi[1];
                rj[a][0] = pj[0]; rj[a][1] = pj[1];
            }
            #pragma unroll
            for (int a = 0; a < 4; ++a)
                #pragma unroll
                for (int d = 0; d < 4; ++d) {
                    fma2(acc[a * 4 + d], ri[a][0], rj[d][0]);
                    fma2(acc[a * 4 + d], ri[a][1], rj[d][1]);
                }
        }
        #pragma unroll
        for (int e = 0; e < 16; ++e) {
            float2 f = unpack2(acc[e]);
            red[tile * 64 + e * 4 + slice] = f.x + f.y;
        }
    } else if (tid < 120) {
        const int r = tid - 100;
        const ull ones = pack2(1.f, 1.f);
        ull acc = 0;
        const ull* pr = (const ull*)&ys[r * YSS];
        for (int t2 = 0; t2 < 128; ++t2) fma2(acc, pr[t2], ones);
        float2 f = unpack2(acc);
        g_part[chunk][b][400 + r] = f.x + f.y;
    }
    __syncthreads();

    for (int p = tid; p < 400; p += 128) {
        int i = p / 20, j = p % 20;
        int tile = (i / 4) * 5 + (j / 4);
        int e = (i % 4) * 4 + (j % 4);
        const float* rp = &red[tile * 64 + e * 4];
        g_part[chunk][b][p] = rp[0] + rp[1] + rp[2] + rp[3];
    }
}

// ---------------------------------------------------------------------------
// Eig: one warp per matrix, EIG_WPB matrices per block (latency hiding via
// warp interleave). __syncwarp only; per-warp smem workspace.
// ---------------------------------------------------------------------------
__global__ void __launch_bounds__(32 * EIG_WPB)
eig_kernel(const float* __restrict__ clf_w,
           const float* __restrict__ clf_b,
           float* __restrict__ out) {
    __shared__ float S[EIG_WPB][20][21];
    __shared__ float U[EIG_WPB][20][21];
    __shared__ float m[EIG_WPB][20], lw[EIG_WPB][20];
    __shared__ float cs[EIG_WPB][10], sn[EIG_WPB][10];
    __shared__ int   pa[EIG_WPB][10], qa[EIG_WPB][10];

    const int lane = threadIdx.x & 31;
    const int w = threadIdx.x >> 5;
    const int b = blockIdx.x * EIG_WPB + w;

    float (*Sw)[21] = S[w];
    float (*Uw)[21] = U[w];

    if (lane < 20) {
        float acc = 0.f;
        #pragma unroll
        for (int ch = 0; ch < NCHUNK; ++ch) acc += g_part[ch][b][400 + lane];
        m[w][lane] = acc;
    }
    __syncwarp();

    for (int p = lane; p < 400; p += 32) {
        float acc = 0.f;
        #pragma unroll
        for (int ch = 0; ch < NCHUNK; ++ch) acc += g_part[ch][b][p];
        int i = p / 20, j = p % 20;
        Sw[i][j] = (acc - m[w][i] * m[w][j] * (1.0f / TT)) * (1.0f / (TT - 1));
    }
    for (int idx = lane; idx < 400; idx += 32) {
        int i = idx / 20, j = idx % 20;
        Uw[i][j] = (i == j) ? 1.f : 0.f;
    }
    __syncwarp();

    for (int sweep = 0; sweep < NSWEEP; ++sweep) {
        for (int r = 0; r < 19; ++r) {
            if (lane < 10) {
                int p = (lane == 0) ? 0 : 1 + ((lane - 1 + r) % 19);
                int q = 1 + ((18 - lane + r) % 19);
                float app = Sw[p][p], aqq = Sw[q][q], apq = Sw[p][q];
                float c = 1.f, s = 0.f;
                if (fabsf(apq) > 1e-12f) {
                    float tau = __fdividef(aqq - app, 2.f * apq);
                    float t = copysignf(__fdividef(1.f, fabsf(tau) + __fsqrt_rn(1.f + tau * tau)), tau);
                    c = rsqrtf(1.f + t * t);
                    s = t * c;
                }
                cs[w][lane] = c; sn[w][lane] = s; pa[w][lane] = p; qa[w][lane] = q;
            }
            __syncwarp();
            #pragma unroll
            for (int it = 0; it < 7; ++it) {
                int idx = lane + it * 32;
                if (idx < 200) {
                    int pr = idx / 20, k = idx - pr * 20;
                    int p = pa[w][pr], q = qa[w][pr];
                    float c = cs[w][pr], s = sn[w][pr];
                    float akp = Sw[k][p], akq = Sw[k][q];
                    Sw[k][p] = c * akp - s * akq;
                    Sw[k][q] = s * akp + c * akq;
                    float ukp = Uw[k][p], ukq = Uw[k][q];
                    Uw[k][p] = c * ukp - s * ukq;
                    Uw[k][q] = s * ukp + c * ukq;
                }
            }
            __syncwarp();
            #pragma unroll
            for (int it = 0; it < 7; ++it) {
                int idx = lane + it * 32;
                if (idx < 200) {
                    int pr = idx / 20, k = idx - pr * 20;
                    int p = pa[w][pr], q = qa[w][pr];
                    float c = cs[w][pr], s = sn[w][pr];
                    float apk = Sw[p][k], aqk = Sw[q][k];
                    Sw[p][k] = c * apk - s * aqk;
                    Sw[q][k] = s * apk + c * aqk;
                }
            }
            __syncwarp();
        }
    }

    if (lane < 20) lw[w][lane] = logf(fmaxf(Sw[lane][lane], 1e-4f));
    __syncwarp();

    float o0 = 0.f, o1 = 0.f, o2 = 0.f, o3 = 0.f;
    const float SQ2 = 1.41421356237309515f;
    for (int p = lane; p < NPAIR; p += 32) {
        int i = 0, rem = p;
        while (rem >= 20 - i) { rem -= 20 - i; ++i; }
        int j = i + rem;
        float L = 0.f;
        #pragma unroll
        for (int mm = 0; mm < 20; ++mm) L += Uw[i][mm] * lw[w][mm] * Uw[j][mm];
        float z = L * ((i == j) ? 1.f : SQ2);
        o0 += z * clf_w[0 * NPAIR + p];
        o1 += z * clf_w[1 * NPAIR + p];
        o2 += z * clf_w[2 * NPAIR + p];
        o3 += z * clf_w[3 * NPAIR + p];
    }
    #pragma unroll
    for (int off = 16; off; off >>= 1) {
        o0 += __shfl_down_sync(0xffffffffu, o0, off);
        o1 += __shfl_down_sync(0xffffffffu, o1, off);
        o2 += __shfl_down_sync(0xffffffffu, o2, off);
        o3 += __shfl_down_sync(0xffffffffu, o3, off);
    }
    if (lane == 0) {
        out[b * 4 + 0] = o0 + clf_b[0];
        out[b * 4 + 1] = o1 + clf_b[1];
        out[b * 4 + 2] = o2 + clf_b[2];
        out[b * 4 + 3] = o3 + clf_b[3];
    }
}

// ---------------------------------------------------------------------------
extern "C" void kernel_launch(void* const* d_in, const int* in_sizes, int n_in,
                              void* d_out, int out_size) {
    const float* x       = (const float*)d_in[0];
    const float* conv1_w = (const float*)d_in[1];
    const float* conv2_w = (const float*)d_in[3];
    const float* W_bimap = (const float*)d_in[5];
    const float* clf_w   = (const float*)d_in[6];
    const float* clf_b   = (const float*)d_in[7];
    float* out = (float*)d_out;

    prep_kernel<<<10, 256>>>(conv2_w, W_bimap);
    gemm_kernel<<<dim3(NCHUNK, BB), 128>>>(x);
    conv_cov_kernel<<<dim3(NCHUNK, BB), 128>>>(conv1_w);
    eig_kernel<<<BB / EIG_WPB, 32 * EIG_WPB>>>(clf_w, clf_b, out);
}

// round 10
// speedup vs baseline: 1.1681x; 1.1681x over previous
#include <cuda_runtime.h>
#include <math.h>

#define BB 256
#define NCH 32
#define TT 2000
#define NTF 4
#define NSF 40
#define NSUB 20
#define TK 25
#define NPAIR 210
#define NCHUNK 8
#define TC 250
#define ZW 288
#define YSS 258
#define NSWEEP 6

typedef unsigned long long ull;

__device__ float g_W2T[32 * 80];
__device__ float g_z[(size_t)BB * NCHUNK * 80 * ZW];
__device__ float g_part[NCHUNK][BB][420];

__device__ __forceinline__ void fma2(ull& d, ull a, ull b) {
    asm("fma.rn.f32x2 %0, %1, %2, %0;" : "+l"(d) : "l"(a), "l"(b));
}
__device__ __forceinline__ ull pack2(float lo, float hi) {
    ull r; asm("mov.b64 %0, {%1, %2};" : "=l"(r) : "f"(lo), "f"(hi)); return r;
}
__device__ __forceinline__ float2 unpack2(ull v) {
    float2 f; asm("mov.b64 {%0, %1}, %2;" : "=f"(f.x), "=f"(f.y) : "l"(v)); return f;
}

// ---------------------------------------------------------------------------
__global__ void prep_kernel(const float* __restrict__ conv2_w,
                            const float* __restrict__ W_bimap) {
    int idx = blockIdx.x * blockDim.x + threadIdx.x;
    if (idx < 2560) {
        int c = idx / 80, sg = idx % 80;
        int s = sg / 4, g = sg % 4;
        float acc = 0.f;
        #pragma unroll 8
        for (int f = 0; f < NSF; ++f)
            acc += W_bimap[s * NSF + f] * conv2_w[f * 128 + g * 32 + c];
        g_W2T[c * 80 + sg] = acc;
    }
}

// ---------------------------------------------------------------------------
__global__ void __launch_bounds__(128)
gemm_kernel(const float* __restrict__ x) {
    __shared__ float xs[32][ZW];
    __shared__ float w2d[32][160];

    const int tid = threadIdx.x;
    const int chunk = blockIdx.x, b = blockIdx.y;
    const int t0 = chunk * TC;
    const float* __restrict__ xb = x + (size_t)b * NCH * TT;

    for (int idx = tid; idx < 32 * ZW; idx += 128) {
        int c = idx / ZW, tt = idx % ZW;
        int gi = t0 - 12 + tt;
        if (gi < 0) gi = -gi;
        if (gi >= TT) gi = 2 * TT - 2 - gi;
        xs[c][tt] = xb[c * TT + gi];
    }
    for (int idx = tid; idx < 2560; idx += 128) {
        int c = idx / 80, sg = idx % 80;
        float w = g_W2T[idx];
        w2d[c][2 * sg] = w;
        w2d[c][2 * sg + 1] = w;
    }
    __syncthreads();

    const int warp = tid >> 5, lane = tid & 31;
    if (lane < 28) {
        const int tau0 = lane * 10;
        float* zbase = &g_z[((size_t)(b * NCHUNK + chunk) * 80) * ZW];

        #pragma unroll 1
        for (int pass = 0; pass < 5; ++pass) {
            const int sg0 = (pass * 4 + warp) * 4;
            ull acc[4][5];
            #pragma unroll
            for (int q = 0; q < 4; ++q)
                #pragma unroll
                for (int p = 0; p < 5; ++p) acc[q][p] = 0;

            #pragma unroll 2
            for (int c = 0; c < NCH; ++c) {
                const ull* xp = (const ull*)&xs[c][tau0];
                ull xv0 = xp[0], xv1 = xp[1], xv2 = xp[2], xv3 = xp[3], xv4 = xp[4];
                const ull* wdp = (const ull*)&w2d[c][2 * sg0];
                ull wd0 = wdp[0], wd1 = wdp[1], wd2 = wdp[2], wd3 = wdp[3];
                fma2(acc[0][0], xv0, wd0); fma2(acc[0][1], xv1, wd0);
                fma2(acc[0][2], xv2, wd0); fma2(acc[0][3], xv3, wd0);
                fma2(acc[0][4], xv4, wd0);
                fma2(acc[1][0], xv0, wd1); fma2(acc[1][1], xv1, wd1);
                fma2(acc[1][2], xv2, wd1); fma2(acc[1][3], xv3, wd1);
                fma2(acc[1][4], xv4, wd1);
                fma2(acc[2][0], xv0, wd2); fma2(acc[2][1], xv1, wd2);
                fma2(acc[2][2], xv2, wd2); fma2(acc[2][3], xv3, wd2);
                fma2(acc[2][4], xv4, wd2);
                fma2(acc[3][0], xv0, wd3); fma2(acc[3][1], xv1, wd3);
                fma2(acc[3][2], xv2, wd3); fma2(acc[3][3], xv3, wd3);
                fma2(acc[3][4], xv4, wd3);
            }
            #pragma unroll
            for (int q = 0; q < 4; ++q) {
                ull* zr = (ull*)(zbase + (size_t)(sg0 + q) * ZW + tau0);
                #pragma unroll
                for (int p = 0; p < 5; ++p) zr[p] = acc[q][p];
            }
        }
    }
}

// ---------------------------------------------------------------------------
__global__ void __launch_bounds__(128)
conv_cov_kernel(const float* __restrict__ w1) {
    __shared__ float zs[16 * ZW];
    __shared__ float ys[20 * YSS];
    __shared__ float w1p[224];
    float* red = zs;

    const int tid = threadIdx.x;
    const int chunk = blockIdx.x, b = blockIdx.y;
    const float* zbase = &g_z[((size_t)(b * NCHUNK + chunk) * 80) * ZW];

    if (tid < 104) {
        int phase = tid / 52, rem = tid % 52, g = rem / 13, i = rem % 13;
        float lo, hi;
        if (phase == 0) {
            lo = w1[g * TK + 2 * i];
            hi = (i < 12) ? w1[g * TK + 2 * i + 1] : 0.f;
        } else {
            lo = (i == 0) ? 0.f : w1[g * TK + 2 * i - 1];
            hi = w1[g * TK + 2 * i];
        }
        int base = (phase * 4 + g) * 28 + 2 * i;
        w1p[base] = lo; w1p[base + 1] = hi;
    }
    if (tid >= 104 && tid < 120) {
        int s = tid - 104;
        w1p[(s >> 1) * 28 + 26 + (s & 1)] = 0.f;
    }

    float4 pf[9];
    {
        const float4* src = (const float4*)zbase;
        #pragma unroll
        for (int r = 0; r < 9; ++r) {
            int i = tid + r * 128;
            if (i < 16 * ZW / 4) pf[r] = src[i];
        }
    }
    __syncthreads();

    const ull* wp = (const ull*)w1p;

    for (int slb = 0; slb < 5; ++slb) {
        {
            float4* dst = (float4*)zs;
            #pragma unroll
            for (int r = 0; r < 9; ++r) {
                int i = tid + r * 128;
                if (i < 16 * ZW / 4) dst[i] = pf[r];
            }
        }
        __syncthreads();

        if (slb < 4) {
            const float4* src = (const float4*)(zbase + (size_t)(slb + 1) * 16 * ZW);
            #pragma unroll
            for (int r = 0; r < 9; ++r) {
                int i = tid + r * 128;
                if (i < 16 * ZW / 4) pf[r] = src[i];
            }
        }

        {
            const int s_loc = tid >> 5, ti = tid & 31;
            const int tl = ti * 8;
            ull accP[8];
            #pragma unroll
            for (int o = 0; o < 8; ++o) accP[o] = 0;

            #pragma unroll
            for (int g = 0; g < 4; ++g) {
                const ull* zrow = (const ull*)&zs[(s_loc * 4 + g) * ZW + tl];
                ull win[16];
                #pragma unroll
                for (int j = 0; j < 16; ++j) win[j] = zrow[j];
                #pragma unroll
                for (int i = 0; i < 13; ++i) {
                    ull wa = wp[g * 14 + i], wb = wp[(4 + g) * 14 + i];
                    #pragma unroll
                    for (int m = 0; m < 4; ++m) {
                        fma2(accP[2 * m],     win[m + i], wa);
                        fma2(accP[2 * m + 1], win[m + i], wb);
                    }
                }
            }
            const int s = slb * 4 + s_loc;
            #pragma unroll
            for (int m = 0; m < 4; ++m) {
                float2 e = unpack2(accP[2 * m]);
                float2 o = unpack2(accP[2 * m + 1]);
                *(float2*)&ys[s * YSS + tl + 2 * m] = make_float2(e.x + e.y, o.x + o.y);
            }
        }
        __syncthreads();
    }

    if (tid < 120) {
        int s = tid / 6, col = 250 + tid % 6;
        ys[s * YSS + col] = 0.f;
    }
    __syncthreads();

    if (tid < 100) {
        const int tile = tid >> 2, slice = tid & 3;
        const int i0 = (tile / 5) * 4, j0 = (tile % 5) * 4;
        ull acc[16];
        #pragma unroll
        for (int e = 0; e < 16; ++e) acc[e] = 0;
        for (int t4 = slice; t4 < 64; t4 += 4) {
            ull ri[4][2], rj[4][2];
            #pragma unroll
            for (int a = 0; a < 4; ++a) {
                const ull* pi = (const ull*)&ys[(i0 + a) * YSS + 4 * t4];
                const ull* pj = (const ull*)&ys[(j0 + a) * YSS + 4 * t4];
                ri[a][0] = pi[0]; ri[a][1] = pi[1];
                rj[a][0] = pj[0]; rj[a][1] = pj[1];
            }
            #pragma unroll
            for (int a = 0; a < 4; ++a)
                #pragma unroll
                for (int d = 0; d < 4; ++d) {
                    fma2(acc[a * 4 + d], ri[a][0], rj[d][0]);
                    fma2(acc[a * 4 + d], ri[a][1], rj[d][1]);
                }
        }
        #pragma unroll
        for (int e = 0; e < 16; ++e) {
            float2 f = unpack2(acc[e]);
            red[tile * 64 + e * 4 + slice] = f.x + f.y;
        }
    } else if (tid < 120) {
        const int r = tid - 100;
        const ull ones = pack2(1.f, 1.f);
        ull acc = 0;
        const ull* pr = (const ull*)&ys[r * YSS];
        for (int t2 = 0; t2 < 128; ++t2) fma2(acc, pr[t2], ones);
        float2 f = unpack2(acc);
        g_part[chunk][b][400 + r] = f.x + f.y;
    }
    __syncthreads();

    for (int p = tid; p < 400; p += 128) {
        int i = p / 20, j = p % 20;
        int tile = (i / 4) * 5 + (j / 4);
        int e = (i % 4) * 4 + (j % 4);
        const float* rp = &red[tile * 64 + e * 4];
        g_part[chunk][b][p] = rp[0] + rp[1] + rp[2] + rp[3];
    }
}

// ---------------------------------------------------------------------------
// Eig: register-resident rows + shfl exchange. One warp per matrix.
// No smem in the rotation loop, no barriers — pure warp-synchronous.
// ---------------------------------------------------------------------------
__global__ void __launch_bounds__(32)
eig_kernel(const float* __restrict__ clf_w,
           const float* __restrict__ clf_b,
           float* __restrict__ out) {
    __shared__ float Ss[20][21];
    __shared__ float Us[20][21];
    __shared__ float m[20], lws[20];

    const int lane = threadIdx.x;
    const int b = blockIdx.x;
    const unsigned FULL = 0xffffffffu;

    if (lane < 20) {
        float acc = 0.f;
        #pragma unroll
        for (int ch = 0; ch < NCHUNK; ++ch) acc += g_part[ch][b][400 + lane];
        m[lane] = acc;
    }
    __syncwarp();
    for (int p = lane; p < 400; p += 32) {
        float acc = 0.f;
        #pragma unroll
        for (int ch = 0; ch < NCHUNK; ++ch) acc += g_part[ch][b][p];
        int i = p / 20, j = p % 20;
        Ss[i][j] = (acc - m[i] * m[j] * (1.0f / TT)) * (1.0f / (TT - 1));
    }
    __syncwarp();

    // rows into registers (lanes 0..19; others hold zeros)
    float Sr[20], Ur[20];
    #pragma unroll
    for (int j = 0; j < 20; ++j) {
        Sr[j] = (lane < 20) ? Ss[lane][j] : 0.f;
        Ur[j] = (lane == j) ? 1.f : 0.f;
    }

    for (int sweep = 0; sweep < NSWEEP; ++sweep) {
        #pragma unroll
        for (int r = 0; r < 19; ++r) {
            // --- gather (app, apq, aqq) for pair i into lane i ---
            float app_r = 0.f, apq_r = 0.f, aqq_r = 0.f;
            #pragma unroll
            for (int i = 0; i < 10; ++i) {
                const int P = (i == 0) ? 0 : 1 + ((i - 1 + r) % 19);
                const int Q = 1 + ((18 - i + r) % 19);
                float app = __shfl_sync(FULL, Sr[P], P);
                float apq = __shfl_sync(FULL, Sr[Q], P);
                float aqq = __shfl_sync(FULL, Sr[Q], Q);
                if (lane == i) { app_r = app; apq_r = apq; aqq_r = aqq; }
            }
            // --- params for all 10 pairs in parallel (lanes 0..9) ---
            float c_r = 1.f, s_r = 0.f;
            if (fabsf(apq_r) > 1e-12f) {
                float tau = __fdividef(aqq_r - app_r, 2.f * apq_r);
                float t = copysignf(__fdividef(1.f, fabsf(tau) + __fsqrt_rn(1.f + tau * tau)), tau);
                c_r = rsqrtf(1.f + t * t);
                s_r = t * c_r;
            }
            float cb[10], sb[10];
            #pragma unroll
            for (int i = 0; i < 10; ++i) {
                cb[i] = __shfl_sync(FULL, c_r, i);
                sb[i] = __shfl_sync(FULL, s_r, i);
            }
            // --- column update: S and U (pure register ops) ---
            #pragma unroll
            for (int i = 0; i < 10; ++i) {
                const int P = (i == 0) ? 0 : 1 + ((i - 1 + r) % 19);
                const int Q = 1 + ((18 - i + r) % 19);
                float sp = Sr[P], sq = Sr[Q];
                Sr[P] = cb[i] * sp - sb[i] * sq;
                Sr[Q] = sb[i] * sp + cb[i] * sq;
                float up = Ur[P], uq = Ur[Q];
                Ur[P] = cb[i] * up - sb[i] * uq;
                Ur[Q] = sb[i] * up + cb[i] * uq;
            }
            // --- row update: exchange with partner via shfl ---
            int partner, myi; bool isp;
            if (lane == 0)      { partner = 1 + ((18 + r) % 19); myi = 0; isp = true; }
            else if (lane < 20) {
                int v = (lane - 1 - r) % 19; if (v < 0) v += 19;
                if (v <= 8)       { partner = 1 + ((17 - v + r) % 19); myi = v + 1;  isp = true; }
                else if (v == 18) { partner = 0;                        myi = 0;      isp = false; }
                else              { partner = 1 + ((17 - v + r) % 19); myi = 18 - v; isp = false; }
            } else { partner = lane; myi = 0; isp = true; }
            float cc = __shfl_sync(FULL, c_r, myi);
            float ss = __shfl_sync(FULL, s_r, myi);
            float sg = isp ? -ss : ss;
            #pragma unroll
            for (int j = 0; j < 20; ++j) {
                float o = __shfl_sync(FULL, Sr[j], partner);  // lockstep: pre-update vals
                Sr[j] = cc * Sr[j] + sg * o;
            }
        }
    }

    // diagonal extract (static-index select), U dump for classifier
    float d = 0.f;
    #pragma unroll
    for (int j = 0; j < 20; ++j) if (lane == j) d = Sr[j];
    if (lane < 20) {
        lws[lane] = logf(fmaxf(d, 1e-4f));
        #pragma unroll
        for (int j = 0; j < 20; ++j) Us[lane][j] = Ur[j];
    }
    __syncwarp();

    float o0 = 0.f, o1 = 0.f, o2 = 0.f, o3 = 0.f;
    const float SQ2 = 1.41421356237309515f;
    for (int p = lane; p < NPAIR; p += 32) {
        int i = 0, rem = p;
        while (rem >= 20 - i) { rem -= 20 - i; ++i; }
        int j = i + rem;
        float L = 0.f;
        #pragma unroll
        for (int mm = 0; mm < 20; ++mm) L += Us[i][mm] * lws[mm] * Us[j][mm];
        float z = L * ((i == j) ? 1.f : SQ2);
        o0 += z * clf_w[0 * NPAIR + p];
        o1 += z * clf_w[1 * NPAIR + p];
        o2 += z * clf_w[2 * NPAIR + p];
        o3 += z * clf_w[3 * NPAIR + p];
    }
    #pragma unroll
    for (int off = 16; off; off >>= 1) {
        o0 += __shfl_down_sync(FULL, o0, off);
        o1 += __shfl_down_sync(FULL, o1, off);
        o2 += __shfl_down_sync(FULL, o2, off);
        o3 += __shfl_down_sync(FULL, o3, off);
    }
    if (lane == 0) {
        out[b * 4 + 0] = o0 + clf_b[0];
        out[b * 4 + 1] = o1 + clf_b[1];
        out[b * 4 + 2] = o2 + clf_b[2];
        out[b * 4 + 3] = o3 + clf_b[3];
    }
}

// ---------------------------------------------------------------------------
extern "C" void kernel_launch(void* const* d_in, const int* in_sizes, int n_in,
                              void* d_out, int out_size) {
    const float* x       = (const float*)d_in[0];
    const float* conv1_w = (const float*)d_in[1];
    const float* conv2_w = (const float*)d_in[3];
    const float* W_bimap = (const float*)d_in[5];
    const float* clf_w   = (const float*)d_in[6];
    const float* clf_b   = (const float*)d_in[7];
    float* out = (float*)d_out;

    prep_kernel<<<10, 256>>>(conv2_w, W_bimap);
    gemm_kernel<<<dim3(NCHUNK, BB), 128>>>(x);
    conv_cov_kernel<<<dim3(NCHUNK, BB), 128>>>(conv1_w);
    eig_kernel<<<BB, 32>>>(clf_w, clf_b, out);
}

// round 11
// speedup vs baseline: 1.2655x; 1.0834x over previous
#include <cuda_runtime.h>
#include <math.h>

#define BB 256
#define NCH 32
#define TT 2000
#define NTF 4
#define NSF 40
#define NSUB 20
#define TK 25
#define NPAIR 210
#define NCHUNK 8
#define TC 250
#define ZW 288
#define YSS 258
#define NSWEEP 6

typedef unsigned long long ull;

__device__ float g_W2T[32 * 80];               // [c*80 + sg]
__device__ float g_part[NCHUNK][BB][420];

__device__ __forceinline__ void fma2(ull& d, ull a, ull b) {
    asm("fma.rn.f32x2 %0, %1, %2, %0;" : "+l"(d) : "l"(a), "l"(b));
}
__device__ __forceinline__ ull pack2(float lo, float hi) {
    ull r; asm("mov.b64 %0, {%1, %2};" : "=l"(r) : "f"(lo), "f"(hi)); return r;
}
__device__ __forceinline__ float2 unpack2(ull v) {
    float2 f; asm("mov.b64 {%0, %1}, %2;" : "=f"(f.x), "=f"(f.y) : "l"(v)); return f;
}

// ---------------------------------------------------------------------------
__global__ void prep_kernel(const float* __restrict__ conv2_w,
                            const float* __restrict__ W_bimap) {
    int idx = blockIdx.x * blockDim.x + threadIdx.x;
    if (idx < 2560) {
        int c = idx / 80, sg = idx % 80;
        int s = sg / 4, g = sg % 4;
        float acc = 0.f;
        #pragma unroll 8
        for (int f = 0; f < NSF; ++f)
            acc += W_bimap[s * NSF + f] * conv2_w[f * 128 + g * 32 + c];
        g_W2T[c * 80 + sg] = acc;
    }
}

// ---------------------------------------------------------------------------
// Fused: stage A (z = W2 @ x slab, smem->smem GEMM) + stage B (temporal conv)
// + tiled covariance. One block per (chunk, batch). z never leaves smem.
// ---------------------------------------------------------------------------
__global__ void __launch_bounds__(128)
fused_kernel(const float* __restrict__ x, const float* __restrict__ w1) {
    extern __shared__ float smem[];
    float* xs  = smem;                  // 32*ZW      = 9216 floats
    float* zs  = xs + 32 * ZW;          // 16*ZW      = 4608
    float* ys  = zs + 16 * ZW;          // 20*YSS     = 5160
    float* w2d = ys + 20 * YSS;         // 32*160     = 5120
    float* w1p = w2d + 32 * 160;        // 224
    float* red = zs;                    // cov reduction aliases zs (1600 <= 4608)

    const int tid = threadIdx.x;
    const int chunk = blockIdx.x, b = blockIdx.y;
    const int t0 = chunk * TC;
    const float* __restrict__ xb = x + (size_t)b * NCH * TT;

    // stage x tile (reflect at tensor edges)
    for (int idx = tid; idx < 32 * ZW; idx += 128) {
        int c = idx / ZW, tt = idx % ZW;
        int gi = t0 - 12 + tt;
        if (gi < 0) gi = -gi;
        if (gi >= TT) gi = 2 * TT - 2 - gi;
        xs[c * ZW + tt] = xb[c * TT + gi];
    }
    // duplicated projection weights
    for (int idx = tid; idx < 2560; idx += 128) {
        int c = idx / 80, sg = idx % 80;
        float w = g_W2T[idx];
        w2d[c * 160 + 2 * sg]     = w;
        w2d[c * 160 + 2 * sg + 1] = w;
    }
    // packed conv1 weights: slot = phase*4+g, 13 pairs + zero pad
    if (tid < 104) {
        int phase = tid / 52, rem = tid % 52, g = rem / 13, i = rem % 13;
        float lo, hi;
        if (phase == 0) {
            lo = w1[g * TK + 2 * i];
            hi = (i < 12) ? w1[g * TK + 2 * i + 1] : 0.f;
        } else {
            lo = (i == 0) ? 0.f : w1[g * TK + 2 * i - 1];
            hi = w1[g * TK + 2 * i];
        }
        int base = (phase * 4 + g) * 28 + 2 * i;
        w1p[base] = lo; w1p[base + 1] = hi;
    }
    if (tid >= 104 && tid < 120) {
        int s = tid - 104;
        w1p[(s >> 1) * 28 + 26 + (s & 1)] = 0.f;
    }
    __syncthreads();

    const int warp = tid >> 5, lane = tid & 31;
    const ull* wp = (const ull*)w1p;

    for (int slb = 0; slb < 5; ++slb) {
        // ---- stage A: zs[16][ZW] for sg = slb*16 .. +15 (proven gemm loop) ----
        if (lane < 28) {
            const int tau0 = lane * 10;
            const int sg0 = (slb * 4 + warp) * 4;
            ull acc[4][5];
            #pragma unroll
            for (int q = 0; q < 4; ++q)
                #pragma unroll
                for (int p = 0; p < 5; ++p) acc[q][p] = 0;

            #pragma unroll 2
            for (int c = 0; c < NCH; ++c) {
                const ull* xp = (const ull*)&xs[c * ZW + tau0];
                ull xv0 = xp[0], xv1 = xp[1], xv2 = xp[2], xv3 = xp[3], xv4 = xp[4];
                const ull* wdp = (const ull*)&w2d[c * 160 + 2 * sg0];  // broadcast
                ull wd0 = wdp[0], wd1 = wdp[1], wd2 = wdp[2], wd3 = wdp[3];
                fma2(acc[0][0], xv0, wd0); fma2(acc[0][1], xv1, wd0);
                fma2(acc[0][2], xv2, wd0); fma2(acc[0][3], xv3, wd0);
                fma2(acc[0][4], xv4, wd0);
                fma2(acc[1][0], xv0, wd1); fma2(acc[1][1], xv1, wd1);
                fma2(acc[1][2], xv2, wd1); fma2(acc[1][3], xv3, wd1);
                fma2(acc[1][4], xv4, wd1);
                fma2(acc[2][0], xv0, wd2); fma2(acc[2][1], xv1, wd2);
                fma2(acc[2][2], xv2, wd2); fma2(acc[2][3], xv3, wd2);
                fma2(acc[2][4], xv4, wd2);
                fma2(acc[3][0], xv0, wd3); fma2(acc[3][1], xv1, wd3);
                fma2(acc[3][2], xv2, wd3); fma2(acc[3][3], xv3, wd3);
                fma2(acc[3][4], xv4, wd3);
            }
            #pragma unroll
            for (int q = 0; q < 4; ++q) {
                ull* zr = (ull*)&zs[(warp * 4 + q) * ZW + tau0];
                #pragma unroll
                for (int p = 0; p < 5; ++p) zr[p] = acc[q][p];
            }
        }
        __syncthreads();

        // ---- stage B: y[s, tl..tl+7], s = slb*4 + warp ----
        {
            const int tl = lane * 8;
            ull accP[8];
            #pragma unroll
            for (int o = 0; o < 8; ++o) accP[o] = 0;

            #pragma unroll
            for (int g = 0; g < 4; ++g) {
                const ull* zrow = (const ull*)&zs[(warp * 4 + g) * ZW + tl];
                ull win[16];
                #pragma unroll
                for (int j = 0; j < 16; ++j) win[j] = zrow[j];
                #pragma unroll
                for (int i = 0; i < 13; ++i) {
                    ull wa = wp[g * 14 + i], wb = wp[(4 + g) * 14 + i];
                    #pragma unroll
                    for (int m = 0; m < 4; ++m) {
                        fma2(accP[2 * m],     win[m + i], wa);
                        fma2(accP[2 * m + 1], win[m + i], wb);
                    }
                }
            }
            const int s = slb * 4 + warp;
            #pragma unroll
            for (int m = 0; m < 4; ++m) {
                float2 e = unpack2(accP[2 * m]);
                float2 o = unpack2(accP[2 * m + 1]);
                *(float2*)&ys[s * YSS + tl + 2 * m] = make_float2(e.x + e.y, o.x + o.y);
            }
        }
        __syncthreads();
    }

    // zero pad ys columns t = 250..255
    if (tid < 120) {
        int s = tid / 6, col = 250 + tid % 6;
        ys[s * YSS + col] = 0.f;
    }
    __syncthreads();

    // ---- covariance: 25 4x4-tiles x 4 t-slices + 20 means ----
    if (tid < 100) {
        const int tile = tid >> 2, slice = tid & 3;
        const int i0 = (tile / 5) * 4, j0 = (tile % 5) * 4;
        ull acc[16];
        #pragma unroll
        for (int e = 0; e < 16; ++e) acc[e] = 0;
        for (int t4 = slice; t4 < 64; t4 += 4) {
            ull ri[4][2], rj[4][2];
            #pragma unroll
            for (int a = 0; a < 4; ++a) {
                const ull* pi = (const ull*)&ys[(i0 + a) * YSS + 4 * t4];
                const ull* pj = (const ull*)&ys[(j0 + a) * YSS + 4 * t4];
                ri[a][0] = pi[0]; ri[a][1] = pi[1];
                rj[a][0] = pj[0]; rj[a][1] = pj[1];
            }
            #pragma unroll
            for (int a = 0; a < 4; ++a)
                #pragma unroll
                for (int d = 0; d < 4; ++d) {
                    fma2(acc[a * 4 + d], ri[a][0], rj[d][0]);
                    fma2(acc[a * 4 + d], ri[a][1], rj[d][1]);
                }
        }
        #pragma unroll
        for (int e = 0; e < 16; ++e) {
            float2 f = unpack2(acc[e]);
            red[tile * 64 + e * 4 + slice] = f.x + f.y;
        }
    } else if (tid < 120) {
        const int r = tid - 100;
        const ull ones = pack2(1.f, 1.f);
        ull acc = 0;
        const ull* pr = (const ull*)&ys[r * YSS];
        for (int t2 = 0; t2 < 128; ++t2) fma2(acc, pr[t2], ones);
        float2 f = unpack2(acc);
        g_part[chunk][b][400 + r] = f.x + f.y;
    }
    __syncthreads();

    for (int p = tid; p < 400; p += 128) {
        int i = p / 20, j = p % 20;
        int tile = (i / 4) * 5 + (j / 4);
        int e = (i % 4) * 4 + (j % 4);
        const float* rp = &red[tile * 64 + e * 4];
        g_part[chunk][b][p] = rp[0] + rp[1] + rp[2] + rp[3];
    }
}

// ---------------------------------------------------------------------------
// Eig: register-resident rows + shfl exchange. One warp per matrix.
// ---------------------------------------------------------------------------
__global__ void __launch_bounds__(32)
eig_kernel(const float* __restrict__ clf_w,
           const float* __restrict__ clf_b,
           float* __restrict__ out) {
    __shared__ float Ss[20][21];
    __shared__ float Us[20][21];
    __shared__ float m[20], lws[20];

    const int lane = threadIdx.x;
    const int b = blockIdx.x;
    const unsigned FULL = 0xffffffffu;

    if (lane < 20) {
        float acc = 0.f;
        #pragma unroll
        for (int ch = 0; ch < NCHUNK; ++ch) acc += g_part[ch][b][400 + lane];
        m[lane] = acc;
    }
    __syncwarp();
    for (int p = lane; p < 400; p += 32) {
        float acc = 0.f;
        #pragma unroll
        for (int ch = 0; ch < NCHUNK; ++ch) acc += g_part[ch][b][p];
        int i = p / 20, j = p % 20;
        Ss[i][j] = (acc - m[i] * m[j] * (1.0f / TT)) * (1.0f / (TT - 1));
    }
    __syncwarp();

    float Sr[20], Ur[20];
    #pragma unroll
    for (int j = 0; j < 20; ++j) {
        Sr[j] = (lane < 20) ? Ss[lane][j] : 0.f;
        Ur[j] = (lane == j) ? 1.f : 0.f;
    }

    for (int sweep = 0; sweep < NSWEEP; ++sweep) {
        #pragma unroll
        for (int r = 0; r < 19; ++r) {
            float app_r = 0.f, apq_r = 0.f, aqq_r = 0.f;
            #pragma unroll
            for (int i = 0; i < 10; ++i) {
                const int P = (i == 0) ? 0 : 1 + ((i - 1 + r) % 19);
                const int Q = 1 + ((18 - i + r) % 19);
                float app = __shfl_sync(FULL, Sr[P], P);
                float apq = __shfl_sync(FULL, Sr[Q], P);
                float aqq = __shfl_sync(FULL, Sr[Q], Q);
                if (lane == i) { app_r = app; apq_r = apq; aqq_r = aqq; }
            }
            float c_r = 1.f, s_r = 0.f;
            if (fabsf(apq_r) > 1e-12f) {
                float tau = __fdividef(aqq_r - app_r, 2.f * apq_r);
                float t = copysignf(__fdividef(1.f, fabsf(tau) + __fsqrt_rn(1.f + tau * tau)), tau);
                c_r = rsqrtf(1.f + t * t);
                s_r = t * c_r;
            }
            float cb[10], sb[10];
            #pragma unroll
            for (int i = 0; i < 10; ++i) {
                cb[i] = __shfl_sync(FULL, c_r, i);
                sb[i] = __shfl_sync(FULL, s_r, i);
            }
            #pragma unroll
            for (int i = 0; i < 10; ++i) {
                const int P = (i == 0) ? 0 : 1 + ((i - 1 + r) % 19);
                const int Q = 1 + ((18 - i + r) % 19);
                float sp = Sr[P], sq = Sr[Q];
                Sr[P] = cb[i] * sp - sb[i] * sq;
                Sr[Q] = sb[i] * sp + cb[i] * sq;
                float up = Ur[P], uq = Ur[Q];
                Ur[P] = cb[i] * up - sb[i] * uq;
                Ur[Q] = sb[i] * up + cb[i] * uq;
            }
            int partner, myi; bool isp;
            if (lane == 0)      { partner = 1 + ((18 + r) % 19); myi = 0; isp = true; }
            else if (lane < 20) {
                int v = (lane - 1 - r) % 19; if (v < 0) v += 19;
                if (v <= 8)       { partner = 1 + ((17 - v + r) % 19); myi = v + 1;  isp = true; }
                else if (v == 18) { partner = 0;                        myi = 0;      isp = false; }
                else              { partner = 1 + ((17 - v + r) % 19); myi = 18 - v; isp = false; }
            } else { partner = lane; myi = 0; isp = true; }
            float cc = __shfl_sync(FULL, c_r, myi);
            float ss = __shfl_sync(FULL, s_r, myi);
            float sg = isp ? -ss : ss;
            #pragma unroll
            for (int j = 0; j < 20; ++j) {
                float o = __shfl_sync(FULL, Sr[j], partner);
                Sr[j] = cc * Sr[j] + sg * o;
            }
        }
    }

    float d = 0.f;
    #pragma unroll
    for (int j = 0; j < 20; ++j) if (lane == j) d = Sr[j];
    if (lane < 20) {
        lws[lane] = logf(fmaxf(d, 1e-4f));
        #pragma unroll
        for (int j = 0; j < 20; ++j) Us[lane][j] = Ur[j];
    }
    __syncwarp();

    float o0 = 0.f, o1 = 0.f, o2 = 0.f, o3 = 0.f;
    const float SQ2 = 1.41421356237309515f;
    for (int p = lane; p < NPAIR; p += 32) {
        int i = 0, rem = p;
        while (rem >= 20 - i) { rem -= 20 - i; ++i; }
        int j = i + rem;
        float L = 0.f;
        #pragma unroll
        for (int mm = 0; mm < 20; ++mm) L += Us[i][mm] * lws[mm] * Us[j][mm];
        float z = L * ((i == j) ? 1.f : SQ2);
        o0 += z * clf_w[0 * NPAIR + p];
        o1 += z * clf_w[1 * NPAIR + p];
        o2 += z * clf_w[2 * NPAIR + p];
        o3 += z * clf_w[3 * NPAIR + p];
    }
    #pragma unroll
    for (int off = 16; off; off >>= 1) {
        o0 += __shfl_down_sync(FULL, o0, off);
        o1 += __shfl_down_sync(FULL, o1, off);
        o2 += __shfl_down_sync(FULL, o2, off);
        o3 += __shfl_down_sync(FULL, o3, off);
    }
    if (lane == 0) {
        out[b * 4 + 0] = o0 + clf_b[0];
        out[b * 4 + 1] = o1 + clf_b[1];
        out[b * 4 + 2] = o2 + clf_b[2];
        out[b * 4 + 3] = o3 + clf_b[3];
    }
}

// ---------------------------------------------------------------------------
extern "C" void kernel_launch(void* const* d_in, const int* in_sizes, int n_in,
                              void* d_out, int out_size) {
    const float* x       = (const float*)d_in[0];
    const float* conv1_w = (const float*)d_in[1];
    const float* conv2_w = (const float*)d_in[3];
    const float* W_bimap = (const float*)d_in[5];
    const float* clf_w   = (const float*)d_in[6];
    const float* clf_b   = (const float*)d_in[7];
    float* out = (float*)d_out;

    size_t smem_bytes = (size_t)(32 * ZW + 16 * ZW + 20 * YSS + 32 * 160 + 224) * sizeof(float);
    cudaFuncSetAttribute(fused_kernel,
                         cudaFuncAttributeMaxDynamicSharedMemorySize,
                         (int)smem_bytes);

    prep_kernel<<<10, 256>>>(conv2_w, W_bimap);
    fused_kernel<<<dim3(NCHUNK, BB), 128, smem_bytes>>>(x, conv1_w);
    eig_kernel<<<BB, 32>>>(clf_w, clf_b, out);
}

// round 12
// speedup vs baseline: 1.6158x; 1.2768x over previous
#include <cuda_runtime.h>
#include <math.h>

#define BB 256
#define NCH 32
#define TT 2000
#define NTF 4
#define NSF 40
#define NSUB 20
#define TK 25
#define NPAIR 210
#define NCHUNK 8
#define TC 250
#define ZW 280
#define YSS 258
#define NSWEEP 5

typedef unsigned long long ull;

__device__ float g_W2T[32 * 80];               // [c*80 + sg]
__device__ float g_part[NCHUNK][BB][420];

__device__ __forceinline__ void fma2(ull& d, ull a, ull b) {
    asm("fma.rn.f32x2 %0, %1, %2, %0;" : "+l"(d) : "l"(a), "l"(b));
}
__device__ __forceinline__ ull pack2(float lo, float hi) {
    ull r; asm("mov.b64 %0, {%1, %2};" : "=l"(r) : "f"(lo), "f"(hi)); return r;
}
__device__ __forceinline__ float2 unpack2(ull v) {
    float2 f; asm("mov.b64 {%0, %1}, %2;" : "=f"(f.x), "=f"(f.y) : "l"(v)); return f;
}

// ---------------------------------------------------------------------------
__global__ void prep_kernel(const float* __restrict__ conv2_w,
                            const float* __restrict__ W_bimap) {
    int idx = blockIdx.x * blockDim.x + threadIdx.x;
    if (idx < 2560) {
        int c = idx / 80, sg = idx % 80;
        int s = sg / 4, g = sg % 4;
        float acc = 0.f;
        #pragma unroll 8
        for (int f = 0; f < NSF; ++f)
            acc += W_bimap[s * NSF + f] * conv2_w[f * 128 + g * 32 + c];
        g_W2T[c * 80 + sg] = acc;
    }
}

// ---------------------------------------------------------------------------
// Fused, software-pipelined: warps 0-3 produce z (GEMM) for slab n+1 while
// warps 4-7 consume slab n (temporal conv -> ys). zs double-buffered in smem.
// Then tiled covariance by all warps. One block per (chunk, batch).
// ---------------------------------------------------------------------------
__global__ void __launch_bounds__(256)
fused_kernel(const float* __restrict__ x, const float* __restrict__ w1) {
    extern __shared__ float smem[];
    float* xs  = smem;                  // 32*280 = 8960
    float* zs0 = xs + 32 * ZW;          // 16*280 = 4480
    float* zs1 = zs0 + 16 * ZW;         // 16*280 = 4480
    float* ys  = zs1 + 16 * ZW;         // 20*258 = 5160
    float* w2t = ys + 20 * YSS;         // 2560
    float* w1p = w2t + 2560;            // 224
    float* red = zs0;                   // cov reduction aliases zs (3200 <= 8960)

    const int tid = threadIdx.x;
    const int chunk = blockIdx.x, b = blockIdx.y;
    const int t0 = chunk * TC;
    const float* __restrict__ xb = x + (size_t)b * NCH * TT;

    // stage x tile (reflect at tensor edges)
    for (int idx = tid; idx < 32 * ZW; idx += 256) {
        int c = idx / ZW, tt = idx % ZW;
        int gi = t0 - 12 + tt;
        if (gi < 0) gi = -gi;
        if (gi >= TT) gi = 2 * TT - 2 - gi;
        xs[c * ZW + tt] = xb[c * TT + gi];
    }
    for (int idx = tid; idx < 2560; idx += 256) w2t[idx] = g_W2T[idx];
    // packed conv1 weights: slot = phase*4+g, 13 pairs + zero pad
    if (tid < 104) {
        int phase = tid / 52, rem = tid % 52, g = rem / 13, i = rem % 13;
        float lo, hi;
        if (phase == 0) {
            lo = w1[g * TK + 2 * i];
            hi = (i < 12) ? w1[g * TK + 2 * i + 1] : 0.f;
        } else {
            lo = (i == 0) ? 0.f : w1[g * TK + 2 * i - 1];
            hi = w1[g * TK + 2 * i];
        }
        int base = (phase * 4 + g) * 28 + 2 * i;
        w1p[base] = lo; w1p[base + 1] = hi;
    }
    if (tid >= 104 && tid < 120) {
        int s = tid - 104;
        w1p[(s >> 1) * 28 + 26 + (s & 1)] = 0.f;
    }
    __syncthreads();

    const int warp = tid >> 5, lane = tid & 31;
    const ull* wp = (const ull*)w1p;

    // ---- stage A producer: quad `warp` (0..3) of slab slb into zbuf ----
    auto produceA = [&](int slb, float* zbuf) {
        if (lane >= 28) return;
        const int tau0 = lane * 10;
        const int sg0 = (slb * 4 + warp) * 4;
        ull acc[4][5];
        #pragma unroll
        for (int q = 0; q < 4; ++q)
            #pragma unroll
            for (int p = 0; p < 5; ++p) acc[q][p] = 0;

        #pragma unroll 2
        for (int c = 0; c < NCH; ++c) {
            const ull* xp = (const ull*)&xs[c * ZW + tau0];
            ull xv0 = xp[0], xv1 = xp[1], xv2 = xp[2], xv3 = xp[3], xv4 = xp[4];
            float4 wq = *(const float4*)&w2t[c * 80 + sg0];   // broadcast LDS.128
            ull wd0 = pack2(wq.x, wq.x), wd1 = pack2(wq.y, wq.y);
            ull wd2 = pack2(wq.z, wq.z), wd3 = pack2(wq.w, wq.w);
            fma2(acc[0][0], xv0, wd0); fma2(acc[0][1], xv1, wd0);
            fma2(acc[0][2], xv2, wd0); fma2(acc[0][3], xv3, wd0);
            fma2(acc[0][4], xv4, wd0);
            fma2(acc[1][0], xv0, wd1); fma2(acc[1][1], xv1, wd1);
            fma2(acc[1][2], xv2, wd1); fma2(acc[1][3], xv3, wd1);
            fma2(acc[1][4], xv4, wd1);
            fma2(acc[2][0], xv0, wd2); fma2(acc[2][1], xv1, wd2);
            fma2(acc[2][2], xv2, wd2); fma2(acc[2][3], xv3, wd2);
            fma2(acc[2][4], xv4, wd2);
            fma2(acc[3][0], xv0, wd3); fma2(acc[3][1], xv1, wd3);
            fma2(acc[3][2], xv2, wd3); fma2(acc[3][3], xv3, wd3);
            fma2(acc[3][4], xv4, wd3);
        }
        #pragma unroll
        for (int q = 0; q < 4; ++q) {
            ull* zr = (ull*)&zbuf[(warp * 4 + q) * ZW + tau0];
            #pragma unroll
            for (int p = 0; p < 5; ++p) zr[p] = acc[q][p];
        }
    };

    // ---- stage B consumer: s = slb*4 + (warp-4), taus lane*8.. ----
    auto consumeB = [&](int slb, const float* zbuf) {
        const int s_loc = warp - 4;
        const int tl = lane * 8;
        ull accP[8];
        #pragma unroll
        for (int o = 0; o < 8; ++o) accP[o] = 0;

        #pragma unroll
        for (int g = 0; g < 4; ++g) {
            const ull* zrow = (const ull*)&zbuf[(s_loc * 4 + g) * ZW + tl];
            ull win[16];
            #pragma unroll
            for (int j = 0; j < 16; ++j) win[j] = zrow[j];
            #pragma unroll
            for (int i = 0; i < 13; ++i) {
                ull wa = wp[g * 14 + i], wb = wp[(4 + g) * 14 + i];
                #pragma unroll
                for (int m = 0; m < 4; ++m) {
                    fma2(accP[2 * m],     win[m + i], wa);
                    fma2(accP[2 * m + 1], win[m + i], wb);
                }
            }
        }
        const int s = slb * 4 + s_loc;
        #pragma unroll
        for (int m = 0; m < 4; ++m) {
            float2 e = unpack2(accP[2 * m]);
            float2 o = unpack2(accP[2 * m + 1]);
            *(float2*)&ys[s * YSS + tl + 2 * m] = make_float2(e.x + e.y, o.x + o.y);
        }
    };

    // software pipeline: A(n+1) || B(n)
    if (warp < 4) produceA(0, zs0);
    __syncthreads();
    #pragma unroll
    for (int n = 0; n < 5; ++n) {
        if (warp < 4) {
            if (n < 4) produceA(n + 1, (n & 1) ? zs0 : zs1);
        } else {
            consumeB(n, (n & 1) ? zs1 : zs0);
        }
        __syncthreads();
    }

    // zero pad ys columns t = 250..255
    if (tid < 120) {
        int s = tid / 6, col = 250 + tid % 6;
        ys[s * YSS + col] = 0.f;
    }
    __syncthreads();

    // ---- covariance: 25 4x4-tiles x 8 t-slices (200 thr) + 20 means ----
    if (tid < 200) {
        const int tile = tid >> 3, slice = tid & 7;
        const int i0 = (tile / 5) * 4, j0 = (tile % 5) * 4;
        ull acc[16];
        #pragma unroll
        for (int e = 0; e < 16; ++e) acc[e] = 0;
        for (int t4 = slice; t4 < 64; t4 += 8) {
            ull ri[4][2], rj[4][2];
            #pragma unroll
            for (int a = 0; a < 4; ++a) {
                const ull* pi = (const ull*)&ys[(i0 + a) * YSS + 4 * t4];
                const ull* pj = (const ull*)&ys[(j0 + a) * YSS + 4 * t4];
                ri[a][0] = pi[0]; ri[a][1] = pi[1];
                rj[a][0] = pj[0]; rj[a][1] = pj[1];
            }
            #pragma unroll
            for (int a = 0; a < 4; ++a)
                #pragma unroll
                for (int d = 0; d < 4; ++d) {
                    fma2(acc[a * 4 + d], ri[a][0], rj[d][0]);
                    fma2(acc[a * 4 + d], ri[a][1], rj[d][1]);
                }
        }
        #pragma unroll
        for (int e = 0; e < 16; ++e) {
            float2 f = unpack2(acc[e]);
            red[tile * 128 + e * 8 + slice] = f.x + f.y;
        }
    } else if (tid < 240) {
        const int r = (tid - 200) >> 1, half = (tid - 200) & 1;
        const ull ones = pack2(1.f, 1.f);
        ull acc = 0;
        const ull* pr = (const ull*)&ys[r * YSS] + half * 64;
        const int n2 = half ? 61 : 64;   // floats 0..127 | 128..249
        for (int t2 = 0; t2 < n2; ++t2) fma2(acc, pr[t2], ones);
        float2 f = unpack2(acc);
        ys[r * YSS + 256 + half] = f.x + f.y;   // stash partials in ys pad
    }
    __syncthreads();

    if (tid < 20)
        g_part[chunk][b][400 + tid] = ys[tid * YSS + 256] + ys[tid * YSS + 257];
    for (int p = tid; p < 400; p += 256) {
        int i = p / 20, j = p % 20;
        int tile = (i / 4) * 5 + (j / 4);
        int e = (i % 4) * 4 + (j % 4);
        const float* rp = &red[tile * 128 + e * 8];
        g_part[chunk][b][p] = ((rp[0] + rp[1]) + (rp[2] + rp[3]))
                            + ((rp[4] + rp[5]) + (rp[6] + rp[7]));
    }
}

// ---------------------------------------------------------------------------
// Eig: register-resident rows + shfl exchange. One warp per matrix.
// ---------------------------------------------------------------------------
__global__ void __launch_bounds__(32)
eig_kernel(const float* __restrict__ clf_w,
           const float* __restrict__ clf_b,
           float* __restrict__ out) {
    __shared__ float Ss[20][21];
    __shared__ float Us[20][21];
    __shared__ float m[20], lws[20];

    const int lane = threadIdx.x;
    const int b = blockIdx.x;
    const unsigned FULL = 0xffffffffu;

    if (lane < 20) {
        float acc = 0.f;
        #pragma unroll
        for (int ch = 0; ch < NCHUNK; ++ch) acc += g_part[ch][b][400 + lane];
        m[lane] = acc;
    }
    __syncwarp();
    for (int p = lane; p < 400; p += 32) {
        float acc = 0.f;
        #pragma unroll
        for (int ch = 0; ch < NCHUNK; ++ch) acc += g_part[ch][b][p];
        int i = p / 20, j = p % 20;
        Ss[i][j] = (acc - m[i] * m[j] * (1.0f / TT)) * (1.0f / (TT - 1));
    }
    __syncwarp();

    float Sr[20], Ur[20];
    #pragma unroll
    for (int j = 0; j < 20; ++j) {
        Sr[j] = (lane < 20) ? Ss[lane][j] : 0.f;
        Ur[j] = (lane == j) ? 1.f : 0.f;
    }

    for (int sweep = 0; sweep < NSWEEP; ++sweep) {
        #pragma unroll
        for (int r = 0; r < 19; ++r) {
            float app_r = 0.f, apq_r = 0.f, aqq_r = 0.f;
            #pragma unroll
            for (int i = 0; i < 10; ++i) {
                const int P = (i == 0) ? 0 : 1 + ((i - 1 + r) % 19);
                const int Q = 1 + ((18 - i + r) % 19);
                float app = __shfl_sync(FULL, Sr[P], P);
                float apq = __shfl_sync(FULL, Sr[Q], P);
                float aqq = __shfl_sync(FULL, Sr[Q], Q);
                if (lane == i) { app_r = app; apq_r = apq; aqq_r = aqq; }
            }
            float c_r = 1.f, s_r = 0.f;
            if (fabsf(apq_r) > 1e-12f) {
                float tau = __fdividef(aqq_r - app_r, 2.f * apq_r);
                float t = copysignf(__fdividef(1.f, fabsf(tau) + __fsqrt_rn(1.f + tau * tau)), tau);
                c_r = rsqrtf(1.f + t * t);
                s_r = t * c_r;
            }
            float cb[10], sb[10];
            #pragma unroll
            for (int i = 0; i < 10; ++i) {
                cb[i] = __shfl_sync(FULL, c_r, i);
                sb[i] = __shfl_sync(FULL, s_r, i);
            }
            #pragma unroll
            for (int i = 0; i < 10; ++i) {
                const int P = (i == 0) ? 0 : 1 + ((i - 1 + r) % 19);
                const int Q = 1 + ((18 - i + r) % 19);
                float sp = Sr[P], sq = Sr[Q];
                Sr[P] = cb[i] * sp - sb[i] * sq;
                Sr[Q] = sb[i] * sp + cb[i] * sq;
                float up = Ur[P], uq = Ur[Q];
                Ur[P] = cb[i] * up - sb[i] * uq;
                Ur[Q] = sb[i] * up + cb[i] * uq;
            }
            int partner, myi; bool isp;
            if (lane == 0)      { partner = 1 + ((18 + r) % 19); myi = 0; isp = true; }
            else if (lane < 20) {
                int v = (lane - 1 - r) % 19; if (v < 0) v += 19;
                if (v <= 8)       { partner = 1 + ((17 - v + r) % 19); myi = v + 1;  isp = true; }
                else if (v == 18) { partner = 0;                        myi = 0;      isp = false; }
                else              { partner = 1 + ((17 - v + r) % 19); myi = 18 - v; isp = false; }
            } else { partner = lane; myi = 0; isp = true; }
            float cc = __shfl_sync(FULL, c_r, myi);
            float ss = __shfl_sync(FULL, s_r, myi);
            float sg = isp ? -ss : ss;
            #pragma unroll
            for (int j = 0; j < 20; ++j) {
                float o = __shfl_sync(FULL, Sr[j], partner);
                Sr[j] = cc * Sr[j] + sg * o;
            }
        }
    }

    float d = 0.f;
    #pragma unroll
    for (int j = 0; j < 20; ++j) if (lane == j) d = Sr[j];
    if (lane < 20) {
        lws[lane] = logf(fmaxf(d, 1e-4f));
        #pragma unroll
        for (int j = 0; j < 20; ++j) Us[lane][j] = Ur[j];
    }
    __syncwarp();

    float o0 = 0.f, o1 = 0.f, o2 = 0.f, o3 = 0.f;
    const float SQ2 = 1.41421356237309515f;
    for (int p = lane; p < NPAIR; p += 32) {
        int i = 0, rem = p;
        while (rem >= 20 - i) { rem -= 20 - i; ++i; }
        int j = i + rem;
        float L = 0.f;
        #pragma unroll
        for (int mm = 0; mm < 20; ++mm) L += Us[i][mm] * lws[mm] * Us[j][mm];
        float z = L * ((i == j) ? 1.f : SQ2);
        o0 += z * clf_w[0 * NPAIR + p];
        o1 += z * clf_w[1 * NPAIR + p];
        o2 += z * clf_w[2 * NPAIR + p];
        o3 += z * clf_w[3 * NPAIR + p];
    }
    #pragma unroll
    for (int off = 16; off; off >>= 1) {
        o0 += __shfl_down_sync(FULL, o0, off);
        o1 += __shfl_down_sync(FULL, o1, off);
        o2 += __shfl_down_sync(FULL, o2, off);
        o3 += __shfl_down_sync(FULL, o3, off);
    }
    if (lane == 0) {
        out[b * 4 + 0] = o0 + clf_b[0];
        out[b * 4 + 1] = o1 + clf_b[1];
        out[b * 4 + 2] = o2 + clf_b[2];
        out[b * 4 + 3] = o3 + clf_b[3];
    }
}

// ---------------------------------------------------------------------------
extern "C" void kernel_launch(void* const* d_in, const int* in_sizes, int n_in,
                              void* d_out, int out_size) {
    const float* x       = (const float*)d_in[0];
    const float* conv1_w = (const float*)d_in[1];
    const float* conv2_w = (const float*)d_in[3];
    const float* W_bimap = (const float*)d_in[5];
    const float* clf_w   = (const float*)d_in[6];
    const float* clf_b   = (const float*)d_in[7];
    float* out = (float*)d_out;

    size_t smem_bytes = (size_t)(32 * ZW + 32 * ZW + 20 * YSS + 2560 + 224) * sizeof(float);
    cudaFuncSetAttribute(fused_kernel,
                         cudaFuncAttributeMaxDynamicSharedMemorySize,
                         (int)smem_bytes);

    prep_kernel<<<10, 256>>>(conv2_w, W_bimap);
    fused_kernel<<<dim3(NCHUNK, BB), 256, smem_bytes>>>(x, conv1_w);
    eig_kernel<<<BB, 32>>>(clf_w, clf_b, out);
}